// round 2
// baseline (speedup 1.0000x reference)
#include <cuda_runtime.h>
#include <cstdint>

#define BB 4
#define NPTS 20000
#define CC 512
#define MM 1024
#define GRASP_TH 0.1f

#define FPS_THREADS 512
#define FPS_WARPS (FPS_THREADS / 32)

// ---------------- scratch (static device allocations; no cudaMalloc) -------
__device__ float4 g_cp[BB * NPTS];    // compacted xyz (w unused)
__device__ int    g_cidx[BB * NPTS];  // compacted -> original index
__device__ float  g_mind[BB * NPTS];  // FPS running min-dist
__device__ int    g_fps[BB * MM];     // sampled original indices
__device__ int    g_nn[BB * MM * 3];  // 3-NN indices
__device__ float  g_w[BB * MM * 3];   // normalized IDW weights

__device__ __forceinline__ float finf() { return __int_as_float(0x7f800000); }

// ============================================================================
// Kernel 1: per-batch mask compaction + furthest point sampling.
// One block per batch. Order-preserving compaction (argmax tie-break = lowest
// original index == lowest compacted index).
// Distance must match XLA bit-exactly: no FMA, ((dx*dx + dy*dy) + dz*dz).
// ============================================================================
__global__ __launch_bounds__(FPS_THREADS, 1)
void fps_kernel(const float* __restrict__ pc,
                const float* __restrict__ obj,
                const float* __restrict__ gr)
{
    const int b    = blockIdx.x;
    const int tid  = threadIdx.x;
    const int lane = tid & 31;
    const int wid  = tid >> 5;

    __shared__ int   s_wsum[FPS_WARPS];
    __shared__ int   s_base;
    __shared__ float s_rv[FPS_WARPS];
    __shared__ int   s_ri[FPS_WARPS];
    __shared__ int   s_last;
    __shared__ float4 s_lp;

    if (tid == 0) s_base = 0;
    __syncthreads();

    const float* objb = obj + (size_t)b * 2 * NPTS;
    const float* grb  = gr  + (size_t)b * NPTS;
    const float* pcb  = pc  + (size_t)b * NPTS * 3;

    // ---- order-preserving compaction of masked points ----
    for (int start = 0; start < NPTS; start += FPS_THREADS) {
        int i = start + tid;
        bool p = false;
        if (i < NPTS)
            p = (objb[NPTS + i] > objb[i]) && (grb[i] > GRASP_TH);
        unsigned bal = __ballot_sync(0xffffffffu, p);
        int wcnt = __popc(bal);
        int wpre = __popc(bal & ((1u << lane) - 1u));
        if (lane == 0) s_wsum[wid] = wcnt;
        __syncthreads();
        if (tid == 0) {
            int acc = s_base;
            #pragma unroll
            for (int w = 0; w < FPS_WARPS; ++w) {
                int c = s_wsum[w];
                s_wsum[w] = acc;
                acc += c;
            }
            s_base = acc;
        }
        __syncthreads();
        if (p) {
            int pos = s_wsum[wid] + wpre;
            g_cidx[b * NPTS + pos] = i;
            float4 q;
            q.x = pcb[3 * i];
            q.y = pcb[3 * i + 1];
            q.z = pcb[3 * i + 2];
            q.w = 0.0f;
            g_cp[b * NPTS + pos] = q;
        }
        __syncthreads();
    }
    const int cnt = s_base;

    if (cnt == 0) {
        // reference: argmax over all -inf -> index 0 every pick
        for (int j = tid; j < MM; j += FPS_THREADS) g_fps[b * MM + j] = 0;
        return;
    }

    float* mind = g_mind + b * NPTS;
    for (int i = tid; i < cnt; i += FPS_THREADS) mind[i] = finf();
    const float4* cp = g_cp + b * NPTS;
    __syncthreads();

    int last = 0;  // first pick = first masked point = compacted 0
    for (int it = 0; it < MM; ++it) {
        if (tid == 0) {
            g_fps[b * MM + it] = g_cidx[b * NPTS + last];
            s_lp = cp[last];
        }
        __syncthreads();
        const float lx = s_lp.x, ly = s_lp.y, lz = s_lp.z;

        float bV = -1.0f;        // mind >= 0 always
        int   bI = 0x7fffffff;
        for (int i = tid; i < cnt; i += FPS_THREADS) {
            float4 q = cp[i];
            float dx = q.x - lx;
            float dy = q.y - ly;
            float dz = q.z - lz;
            // bit-exact vs XLA: ((dx*dx + dy*dy) + dz*dz), no contraction
            float d = __fadd_rn(__fadd_rn(__fmul_rn(dx, dx),
                                          __fmul_rn(dy, dy)),
                                __fmul_rn(dz, dz));
            float m = fminf(mind[i], d);
            mind[i] = m;
            if (m > bV || (m == bV && i < bI)) { bV = m; bI = i; }
        }
        // warp argmax (value desc, index asc on ties)
        #pragma unroll
        for (int o = 16; o; o >>= 1) {
            float ov = __shfl_down_sync(0xffffffffu, bV, o);
            int   oi = __shfl_down_sync(0xffffffffu, bI, o);
            if (ov > bV || (ov == bV && oi < bI)) { bV = ov; bI = oi; }
        }
        if (lane == 0) { s_rv[wid] = bV; s_ri[wid] = bI; }
        __syncthreads();
        if (tid < 32) {
            bV = (tid < FPS_WARPS) ? s_rv[tid] : -1.0f;
            bI = (tid < FPS_WARPS) ? s_ri[tid] : 0x7fffffff;
            #pragma unroll
            for (int o = FPS_WARPS / 2; o; o >>= 1) {
                float ov = __shfl_down_sync(0xffffffffu, bV, o);
                int   oi = __shfl_down_sync(0xffffffffu, bI, o);
                if (ov > bV || (ov == bV && oi < bI)) { bV = ov; bI = oi; }
            }
            if (tid == 0) s_last = bI;
        }
        __syncthreads();
        last = s_last;
    }
}

// ============================================================================
// Kernel 2: three_nn — 3 nearest neighbors of each sampled point in the FULL
// cloud. Tiled brute force: QB queries/block, SUBS lanes/query, cloud tile in
// shared memory. Numerically forgiving (self-point d=0 dominates weights), so
// FMA is fine here.
// ============================================================================
#define QB 8
#define SUBS 16
#define TNB (QB * SUBS)   // 128 threads
#define TS 2048           // tile points

__global__ __launch_bounds__(TNB, 8)
void nn_kernel(const float* __restrict__ pc)
{
    __shared__ float s_pts[TS * 3];

    const int tid  = threadIdx.x;
    const int ql   = tid / SUBS;
    const int sub  = tid % SUBS;
    const int q    = blockIdx.x * QB + ql;      // 0 .. B*M-1
    const int b    = q / MM;

    const int fidx = g_fps[q];
    const float* pcb = pc + (size_t)b * NPTS * 3;
    const float qx = pcb[3 * fidx];
    const float qy = pcb[3 * fidx + 1];
    const float qz = pcb[3 * fidx + 2];

    float d0 = finf(), d1 = finf(), d2 = finf();
    int   i0 = -1,     i1 = -1,     i2 = -1;

    for (int t0 = 0; t0 < NPTS; t0 += TS) {
        const int ts = min(TS, NPTS - t0);
        __syncthreads();
        for (int j = tid; j < ts * 3; j += TNB)
            s_pts[j] = pcb[t0 * 3 + j];
        __syncthreads();

        for (int j = sub; j < ts; j += SUBS) {
            float dx = s_pts[3 * j]     - qx;
            float dy = s_pts[3 * j + 1] - qy;
            float dz = s_pts[3 * j + 2] - qz;
            float d = fmaf(dz, dz, fmaf(dy, dy, dx * dx));
            if (d < d2) {
                int gi = t0 + j;
                if (d < d1) {
                    if (d < d0) { d2 = d1; i2 = i1; d1 = d0; i1 = i0; d0 = d; i0 = gi; }
                    else        { d2 = d1; i2 = i1; d1 = d;  i1 = gi; }
                } else          { d2 = d;  i2 = gi; }
            }
        }
    }

    // merge top-3 across the 16 lanes of this query (shfl segments of 16)
    #pragma unroll
    for (int off = SUBS / 2; off; off >>= 1) {
        float od0 = __shfl_down_sync(0xffffffffu, d0, off, SUBS);
        float od1 = __shfl_down_sync(0xffffffffu, d1, off, SUBS);
        float od2 = __shfl_down_sync(0xffffffffu, d2, off, SUBS);
        int   oi0 = __shfl_down_sync(0xffffffffu, i0, off, SUBS);
        int   oi1 = __shfl_down_sync(0xffffffffu, i1, off, SUBS);
        int   oi2 = __shfl_down_sync(0xffffffffu, i2, off, SUBS);
        #pragma unroll
        for (int k = 0; k < 3; ++k) {
            float d = (k == 0) ? od0 : (k == 1) ? od1 : od2;
            int   i = (k == 0) ? oi0 : (k == 1) ? oi1 : oi2;
            bool l2 = (d < d2) || (d == d2 && i < i2);
            if (l2) {
                bool l1 = (d < d1) || (d == d1 && i < i1);
                if (l1) {
                    bool l0 = (d < d0) || (d == d0 && i < i0);
                    if (l0) { d2 = d1; i2 = i1; d1 = d0; i1 = i0; d0 = d; i0 = i; }
                    else    { d2 = d1; i2 = i1; d1 = d;  i1 = i; }
                } else      { d2 = d;  i2 = i; }
            }
        }
    }

    if (sub == 0) {
        float e0 = sqrtf(fmaxf(d0, 0.0f));
        float e1 = sqrtf(fmaxf(d1, 0.0f));
        float e2 = sqrtf(fmaxf(d2, 0.0f));
        float w0 = 1.0f / (e0 + 1e-8f);
        float w1 = 1.0f / (e1 + 1e-8f);
        float w2 = 1.0f / (e2 + 1e-8f);
        float s  = __fadd_rn(__fadd_rn(w0, w1), w2);
        g_w[3 * q + 0] = w0 / s;
        g_w[3 * q + 1] = w1 / s;
        g_w[3 * q + 2] = w2 / s;
        g_nn[3 * q + 0] = i0;
        g_nn[3 * q + 1] = i1;
        g_nn[3 * q + 2] = i2;
    }
}

// ============================================================================
// Kernel 3: IDW feature interpolation. out[b,c,m] = sum_k w_k * feat[b,c,nn_k]
// m is the fastest dim -> coalesced output; gathers are L2-resident per row.
// ============================================================================
__global__ __launch_bounds__(256)
void interp_kernel(const float* __restrict__ feat, float* __restrict__ out)
{
    int e = blockIdx.x * blockDim.x + threadIdx.x;
    if (e >= BB * CC * MM) return;
    const int m = e % MM;
    const int c = (e / MM) % CC;
    const int b = e / (MM * CC);
    const int q = b * MM + m;

    const int   j0 = g_nn[3 * q],     j1 = g_nn[3 * q + 1], j2 = g_nn[3 * q + 2];
    const float w0 = g_w[3 * q],      w1 = g_w[3 * q + 1],  w2 = g_w[3 * q + 2];
    const float* f = feat + ((size_t)b * CC + c) * NPTS;
    out[e] = w0 * f[j0] + w1 * f[j1] + w2 * f[j2];
}

// ============================================================================
extern "C" void kernel_launch(void* const* d_in, const int* in_sizes, int n_in,
                              void* d_out, int out_size)
{
    const float* pc   = (const float*)d_in[0];  // (B,N,3)
    const float* feat = (const float*)d_in[1];  // (B,C,N)
    const float* obj  = (const float*)d_in[2];  // (B,2,N)
    const float* gr   = (const float*)d_in[3];  // (B,N)
    float* out = (float*)d_out;                 // (B,C,M)

    fps_kernel<<<BB, FPS_THREADS>>>(pc, obj, gr);
    nn_kernel<<<(BB * MM) / QB, TNB>>>(pc);
    interp_kernel<<<(BB * CC * MM + 255) / 256, 256>>>(feat, out);
}

// round 3
// speedup vs baseline: 1.5793x; 1.5793x over previous
#include <cuda_runtime.h>
#include <cstdint>

#define BB 4
#define NPTS 20000
#define CC 512
#define MM 1024
#define GRASP_TH 0.1f

#define FPS_THREADS 512
#define FPS_WARPS (FPS_THREADS / 32)
#define CAPR 10                      // register-resident points per thread
#define REGN (FPS_THREADS * CAPR)    // 5120 points register-resident

// ---------------- scratch (static device allocations; no cudaMalloc) -------
__device__ float4 g_cp[BB * NPTS];    // compacted xyz (w unused)
__device__ int    g_cidx[BB * NPTS];  // compacted -> original index
__device__ float  g_mind[BB * NPTS];  // FPS running min-dist (fallback region only)
__device__ int    g_fps[BB * MM];     // sampled original indices
__device__ int    g_nn[BB * MM * 3];  // 3-NN indices
__device__ float  g_w[BB * MM * 3];   // normalized IDW weights

__device__ __forceinline__ float finf() { return __int_as_float(0x7f800000); }

// ============================================================================
// Kernel 1: per-batch mask compaction + furthest point sampling.
// One block per batch. State (coords + running min-dist) lives in REGISTERS;
// argmax via REDUX.MAX/MIN; single __syncthreads per iteration (double-buffered
// per-warp results).
// Distance must match XLA bit-exactly: no FMA, ((dx*dx + dy*dy) + dz*dz).
// ============================================================================
__global__ __launch_bounds__(FPS_THREADS, 1)
void fps_kernel(const float* __restrict__ pc,
                const float* __restrict__ obj,
                const float* __restrict__ gr)
{
    const int b    = blockIdx.x;
    const int tid  = threadIdx.x;
    const int lane = tid & 31;
    const int wid  = tid >> 5;

    __shared__ int      s_wsum[FPS_WARPS];
    __shared__ int      s_base;
    __shared__ unsigned s_v[2][FPS_WARPS];
    __shared__ unsigned s_i[2][FPS_WARPS];
    __shared__ float    s_x[2][FPS_WARPS];
    __shared__ float    s_y[2][FPS_WARPS];
    __shared__ float    s_z[2][FPS_WARPS];

    if (tid == 0) s_base = 0;
    __syncthreads();

    const float* objb = obj + (size_t)b * 2 * NPTS;
    const float* grb  = gr  + (size_t)b * NPTS;
    const float* pcb  = pc  + (size_t)b * NPTS * 3;

    // ---- order-preserving compaction of masked points ----
    for (int start = 0; start < NPTS; start += FPS_THREADS) {
        int i = start + tid;
        bool p = false;
        if (i < NPTS)
            p = (objb[NPTS + i] > objb[i]) && (grb[i] > GRASP_TH);
        unsigned bal = __ballot_sync(0xffffffffu, p);
        int wcnt = __popc(bal);
        int wpre = __popc(bal & ((1u << lane) - 1u));
        if (lane == 0) s_wsum[wid] = wcnt;
        __syncthreads();
        if (tid == 0) {
            int acc = s_base;
            #pragma unroll
            for (int w = 0; w < FPS_WARPS; ++w) {
                int c = s_wsum[w];
                s_wsum[w] = acc;
                acc += c;
            }
            s_base = acc;
        }
        __syncthreads();
        if (p) {
            int pos = s_wsum[wid] + wpre;
            g_cidx[b * NPTS + pos] = i;
            float4 q;
            q.x = pcb[3 * i];
            q.y = pcb[3 * i + 1];
            q.z = pcb[3 * i + 2];
            q.w = 0.0f;
            g_cp[b * NPTS + pos] = q;
        }
        __syncthreads();
    }
    const int cnt = s_base;

    if (cnt == 0) {
        // reference: argmax over all -inf -> index 0 every pick
        for (int j = tid; j < MM; j += FPS_THREADS) g_fps[b * MM + j] = 0;
        return;
    }

    const float4* cp = g_cp + b * NPTS;
    const int regCnt = min(cnt, REGN);

    // ---- load owned points into registers ----
    float rx[CAPR], ry[CAPR], rz[CAPR], md[CAPR];
    #pragma unroll
    for (int k = 0; k < CAPR; ++k) {
        int i = tid + (k << 9);
        if (i < regCnt) {
            float4 q = cp[i];
            rx[k] = q.x; ry[k] = q.y; rz[k] = q.z;
        } else {
            rx[k] = 0.0f; ry[k] = 0.0f; rz[k] = 0.0f;
        }
        md[k] = finf();
    }
    // fallback region min-dist init (rare: cnt > 5120)
    float* gmind = g_mind + b * NPTS;
    for (int i = REGN + tid; i < cnt; i += FPS_THREADS) gmind[i] = finf();
    __syncthreads();

    // ---- first pick = compacted point 0 ----
    float4 p0 = cp[0];                  // broadcast LDG, all threads
    float lx = p0.x, ly = p0.y, lz = p0.z;
    if (tid == 0) g_fps[b * MM] = g_cidx[b * NPTS];

    int buf = 0;
    for (int it = 1; it < MM; ++it) {
        // --- update owned minds, track local best (max value, min index) ---
        float    bV = 0.0f;             // sentinel: loses value ties via index
        unsigned bI = 0xffffffffu;
        float    bX = 0.0f, bY = 0.0f, bZ = 0.0f;
        #pragma unroll
        for (int k = 0; k < CAPR; ++k) {
            unsigned i = (unsigned)(tid + (k << 9));
            bool valid = (int)i < regCnt;
            float dx = rx[k] - lx;
            float dy = ry[k] - ly;
            float dz = rz[k] - lz;
            // bit-exact vs XLA: ((dx*dx + dy*dy) + dz*dz), no contraction
            float d = __fadd_rn(__fadd_rn(__fmul_rn(dx, dx),
                                          __fmul_rn(dy, dy)),
                                __fmul_rn(dz, dz));
            float m = fminf(md[k], d);
            md[k] = m;
            bool better = valid && ((m > bV) | ((m == bV) & (i < bI)));
            if (better) { bV = m; bI = i; bX = rx[k]; bY = ry[k]; bZ = rz[k]; }
        }
        // --- fallback region (cnt > REGN): gmem state, usually empty ---
        for (int i = REGN + tid; i < cnt; i += FPS_THREADS) {
            float4 q = cp[i];
            float dx = q.x - lx;
            float dy = q.y - ly;
            float dz = q.z - lz;
            float d = __fadd_rn(__fadd_rn(__fmul_rn(dx, dx),
                                          __fmul_rn(dy, dy)),
                                __fmul_rn(dz, dz));
            float m = fminf(gmind[i], d);
            gmind[i] = m;
            bool better = (m > bV) | ((m == bV) & ((unsigned)i < bI));
            if (better) { bV = m; bI = (unsigned)i; bX = q.x; bY = q.y; bZ = q.z; }
        }

        // --- warp argmax via REDUX (dist >= 0 => f32 bits are u32-monotone) ---
        unsigned vb = __float_as_uint(bV);
        unsigned wv = __reduce_max_sync(0xffffffffu, vb);
        unsigned cand = (vb == wv) ? bI : 0xffffffffu;
        unsigned wi = __reduce_min_sync(0xffffffffu, cand);
        if (vb == wv && bI == wi) {     // exactly the winning lane (idx unique)
            s_v[buf][wid] = wv;
            s_i[buf][wid] = wi;
            s_x[buf][wid] = bX;
            s_y[buf][wid] = bY;
            s_z[buf][wid] = bZ;
        }
        __syncthreads();

        // --- cross-warp argmax: 16 entries, done redundantly in every warp ---
        int j = lane & (FPS_WARPS - 1);
        unsigned vv = s_v[buf][j];
        unsigned ii = s_i[buf][j];
        float    xx = s_x[buf][j];
        float    yy = s_y[buf][j];
        float    zz = s_z[buf][j];
        unsigned gv = __reduce_max_sync(0xffffffffu, vv);
        unsigned c2 = (vv == gv) ? ii : 0xffffffffu;
        unsigned gi = __reduce_min_sync(0xffffffffu, c2);
        unsigned wb = __ballot_sync(0xffffffffu, (vv == gv) & (ii == gi));
        int ls = __ffs(wb) - 1;
        lx = __shfl_sync(0xffffffffu, xx, ls);
        ly = __shfl_sync(0xffffffffu, yy, ls);
        lz = __shfl_sync(0xffffffffu, zz, ls);

        if (tid == 0) g_fps[b * MM + it] = g_cidx[b * NPTS + (int)gi];
        buf ^= 1;
    }
}

// ============================================================================
// Kernel 2: three_nn — 3 nearest neighbors of each sampled point in the FULL
// cloud. Tiled brute force: QB queries/block, SUBS lanes/query, cloud tile in
// shared memory. Numerically forgiving (self-point d=0 dominates weights).
// ============================================================================
#define QB 8
#define SUBS 16
#define TNB (QB * SUBS)   // 128 threads
#define TS 2048           // tile points

__global__ __launch_bounds__(TNB, 8)
void nn_kernel(const float* __restrict__ pc)
{
    __shared__ float s_pts[TS * 3];

    const int tid  = threadIdx.x;
    const int ql   = tid / SUBS;
    const int sub  = tid % SUBS;
    const int q    = blockIdx.x * QB + ql;      // 0 .. B*M-1
    const int b    = q / MM;

    const int fidx = g_fps[q];
    const float* pcb = pc + (size_t)b * NPTS * 3;
    const float qx = pcb[3 * fidx];
    const float qy = pcb[3 * fidx + 1];
    const float qz = pcb[3 * fidx + 2];

    float d0 = finf(), d1 = finf(), d2 = finf();
    int   i0 = -1,     i1 = -1,     i2 = -1;

    for (int t0 = 0; t0 < NPTS; t0 += TS) {
        const int ts = min(TS, NPTS - t0);
        __syncthreads();
        for (int j = tid; j < ts * 3; j += TNB)
            s_pts[j] = pcb[t0 * 3 + j];
        __syncthreads();

        for (int j = sub; j < ts; j += SUBS) {
            float dx = s_pts[3 * j]     - qx;
            float dy = s_pts[3 * j + 1] - qy;
            float dz = s_pts[3 * j + 2] - qz;
            float d = fmaf(dz, dz, fmaf(dy, dy, dx * dx));
            if (d < d2) {
                int gi = t0 + j;
                if (d < d1) {
                    if (d < d0) { d2 = d1; i2 = i1; d1 = d0; i1 = i0; d0 = d; i0 = gi; }
                    else        { d2 = d1; i2 = i1; d1 = d;  i1 = gi; }
                } else          { d2 = d;  i2 = gi; }
            }
        }
    }

    // merge top-3 across the 16 lanes of this query (shfl segments of 16)
    #pragma unroll
    for (int off = SUBS / 2; off; off >>= 1) {
        float od0 = __shfl_down_sync(0xffffffffu, d0, off, SUBS);
        float od1 = __shfl_down_sync(0xffffffffu, d1, off, SUBS);
        float od2 = __shfl_down_sync(0xffffffffu, d2, off, SUBS);
        int   oi0 = __shfl_down_sync(0xffffffffu, i0, off, SUBS);
        int   oi1 = __shfl_down_sync(0xffffffffu, i1, off, SUBS);
        int   oi2 = __shfl_down_sync(0xffffffffu, i2, off, SUBS);
        #pragma unroll
        for (int k = 0; k < 3; ++k) {
            float d = (k == 0) ? od0 : (k == 1) ? od1 : od2;
            int   i = (k == 0) ? oi0 : (k == 1) ? oi1 : oi2;
            bool l2 = (d < d2) || (d == d2 && i < i2);
            if (l2) {
                bool l1 = (d < d1) || (d == d1 && i < i1);
                if (l1) {
                    bool l0 = (d < d0) || (d == d0 && i < i0);
                    if (l0) { d2 = d1; i2 = i1; d1 = d0; i1 = i0; d0 = d; i0 = i; }
                    else    { d2 = d1; i2 = i1; d1 = d;  i1 = i; }
                } else      { d2 = d;  i2 = i; }
            }
        }
    }

    if (sub == 0) {
        float e0 = sqrtf(fmaxf(d0, 0.0f));
        float e1 = sqrtf(fmaxf(d1, 0.0f));
        float e2 = sqrtf(fmaxf(d2, 0.0f));
        float w0 = 1.0f / (e0 + 1e-8f);
        float w1 = 1.0f / (e1 + 1e-8f);
        float w2 = 1.0f / (e2 + 1e-8f);
        float s  = __fadd_rn(__fadd_rn(w0, w1), w2);
        g_w[3 * q + 0] = w0 / s;
        g_w[3 * q + 1] = w1 / s;
        g_w[3 * q + 2] = w2 / s;
        g_nn[3 * q + 0] = i0;
        g_nn[3 * q + 1] = i1;
        g_nn[3 * q + 2] = i2;
    }
}

// ============================================================================
// Kernel 3: IDW feature interpolation. out[b,c,m] = sum_k w_k * feat[b,c,nn_k]
// ============================================================================
__global__ __launch_bounds__(256)
void interp_kernel(const float* __restrict__ feat, float* __restrict__ out)
{
    int e = blockIdx.x * blockDim.x + threadIdx.x;
    if (e >= BB * CC * MM) return;
    const int m = e % MM;
    const int c = (e / MM) % CC;
    const int b = e / (MM * CC);
    const int q = b * MM + m;

    const int   j0 = g_nn[3 * q],     j1 = g_nn[3 * q + 1], j2 = g_nn[3 * q + 2];
    const float w0 = g_w[3 * q],      w1 = g_w[3 * q + 1],  w2 = g_w[3 * q + 2];
    const float* f = feat + ((size_t)b * CC + c) * NPTS;
    out[e] = w0 * f[j0] + w1 * f[j1] + w2 * f[j2];
}

// ============================================================================
extern "C" void kernel_launch(void* const* d_in, const int* in_sizes, int n_in,
                              void* d_out, int out_size)
{
    const float* pc   = (const float*)d_in[0];  // (B,N,3)
    const float* feat = (const float*)d_in[1];  // (B,C,N)
    const float* obj  = (const float*)d_in[2];  // (B,2,N)
    const float* gr   = (const float*)d_in[3];  // (B,N)
    float* out = (float*)d_out;                 // (B,C,M)

    fps_kernel<<<BB, FPS_THREADS>>>(pc, obj, gr);
    nn_kernel<<<(BB * MM) / QB, TNB>>>(pc);
    interp_kernel<<<(BB * CC * MM + 255) / 256, 256>>>(feat, out);
}